// round 11
// baseline (speedup 1.0000x reference)
#include <cuda_runtime.h>
#include <math.h>

// Problem constants (fixed by the reference setup)
constexpr int NN   = 512;
constexpr int JJ   = 20000;
constexpr int DIMM = JJ - 1;    // 19999 softmax logit columns (pivot dropped)
constexpr int PP   = 8;
constexpr int JT   = 256;                         // threads per block (j dimension)
constexpr int JB   = (JJ + JT - 1) / JT;          // 79 j-blocks
constexpr int RB   = 16;                          // row chunks
constexpr int ROWS_PER = NN / RB;                 // 32 rows per block
constexpr int LFMAX = 2048;                       // log-factorial table size

// Scratch (device globals: no allocations allowed)
__device__ float  g_r[JJ];          // 1 / softplus(phi)
__device__ float  g_logr[JJ];       // log(r)
__device__ float  g_lgr[JJ];        // lgamma(r)
__device__ float  g_lf[LFMAX];      // lgamma(i + 1) = log(i!)
__device__ float  g_pexp[JB * NN];  // partial sum of exp(logits) per (jblock, row)
__device__ float  g_ps[JB * NN];    // partial sum of Y per (jblock, row)
__device__ float  g_lse[NN];        // logsumexp per row
__device__ float  g_logs[NN];       // log(sum Y) per row
__device__ float  g_s[NN];          // sum Y per row
__device__ double g_part[JB * RB];  // per-block loglik partials

// ---------------------------------------------------------------------------
// Kernel 1: per-gene precompute + log-factorial table
// ---------------------------------------------------------------------------
__global__ void k_prep(const float* __restrict__ phi) {
    int i = blockIdx.x * blockDim.x + threadIdx.x;
    if (i < JJ) {
        float ph = phi[i];
        // softplus(x) = max(x,0) + log1p(exp(-|x|))
        float sp = fmaxf(ph, 0.0f) + log1pf(expf(-fabsf(ph)));
        float r  = 1.0f / sp;
        g_r[i]    = r;
        g_logr[i] = -logf(sp);      // log(1/sp)
        g_lgr[i]  = lgammaf(r);
    }
    if (i < LFMAX) {
        g_lf[i] = lgammaf((float)i + 1.0f);
    }
}

// ---------------------------------------------------------------------------
// Kernel 2: j-major row statistics: partial sum(exp(logit)) and sum(Y) per row
// Each thread owns ONE j column (mu + 8 betas hoisted into registers) and
// loops over 32 rows; 2-stage deterministic reduction via g_pexp/g_ps.
// ---------------------------------------------------------------------------
__global__ void k_rowpart(const float* __restrict__ mu,
                          const float* __restrict__ beta,
                          const float* __restrict__ X,
                          const float* __restrict__ Y) {
    const int tid  = threadIdx.x;
    const int j    = blockIdx.x * JT + tid;
    const bool valid = (j < JJ);
    const bool hasb  = (j < DIMM);

    float mu_j = 0.0f;
    float b[PP];
#pragma unroll
    for (int p = 0; p < PP; p++) b[p] = 0.0f;
    if (hasb) {
        mu_j = mu[j];
#pragma unroll
        for (int p = 0; p < PP; p++) b[p] = beta[(size_t)p * DIMM + j];
    }

    const int n0 = blockIdx.y * ROWS_PER;
    __shared__ float sx[ROWS_PER * PP];   // X rows for this chunk (256 floats)
    if (tid < ROWS_PER * PP) sx[tid] = X[(size_t)n0 * PP + tid];
    __shared__ float s_e[8], s_y[8];
    __syncthreads();

    const int lane = tid & 31, wid = tid >> 5;

    for (int ni = 0; ni < ROWS_PER; ni++) {
        const int n = n0 + ni;
        float xb = mu_j;
#pragma unroll
        for (int p = 0; p < PP; p++) xb = fmaf(sx[ni * PP + p], b[p], xb);
        // pivot column (j == DIMM): mu_j = b = 0 -> xb = 0 -> exp = 1 (correct)
        float e = valid ? expf(xb) : 0.0f;
        float y = valid ? Y[(size_t)n * JJ + j] : 0.0f;
#pragma unroll
        for (int off = 16; off > 0; off >>= 1) {
            e += __shfl_down_sync(0xffffffffu, e, off);
            y += __shfl_down_sync(0xffffffffu, y, off);
        }
        if (lane == 0) { s_e[wid] = e; s_y[wid] = y; }
        __syncthreads();
        if (wid == 0) {
            float ee = (lane < 8) ? s_e[lane] : 0.0f;
            float yy = (lane < 8) ? s_y[lane] : 0.0f;
#pragma unroll
            for (int off = 4; off > 0; off >>= 1) {
                ee += __shfl_down_sync(0xffffffffu, ee, off);
                yy += __shfl_down_sync(0xffffffffu, yy, off);
            }
            if (lane == 0) {
                g_pexp[blockIdx.x * NN + n] = ee;
                g_ps[blockIdx.x * NN + n]   = yy;
            }
        }
        __syncthreads();
    }
}

// ---------------------------------------------------------------------------
// Kernel 3: finalize row stats (deterministic serial reduce over 79 partials)
// ---------------------------------------------------------------------------
__global__ void k_rowfinal() {
    int n = blockIdx.x * blockDim.x + threadIdx.x;
    if (n >= NN) return;
    double se = 0.0;
    float  ss = 0.0f;
    for (int i = 0; i < JB; i++) {
        se += (double)g_pexp[i * NN + n];   // coalesced across n
        ss += g_ps[i * NN + n];             // exact: integer partial sums < 2^24
    }
    g_lse[n]  = (float)log(se);
    g_s[n]    = ss;
    g_logs[n] = logf(ss);
}

// ---------------------------------------------------------------------------
// Kernel 4: main NB log-likelihood accumulation (j-major, double accumulate)
// ---------------------------------------------------------------------------
__global__ void k_main(const float* __restrict__ mu,
                       const float* __restrict__ beta,
                       const float* __restrict__ X,
                       const float* __restrict__ Y) {
    const int tid  = threadIdx.x;
    const int j    = blockIdx.x * JT + tid;
    const bool valid = (j < JJ);
    const bool hasb  = (j < DIMM);

    float r = 1.0f, logr = 0.0f, lgr = 0.0f;
    if (valid) { r = g_r[j]; logr = g_logr[j]; lgr = g_lgr[j]; }
    float mu_j = 0.0f;
    float b[PP];
#pragma unroll
    for (int p = 0; p < PP; p++) b[p] = 0.0f;
    if (hasb) {
        mu_j = mu[j];
#pragma unroll
        for (int p = 0; p < PP; p++) b[p] = beta[(size_t)p * DIMM + j];
    }

    const int n0 = blockIdx.y * ROWS_PER;
    __shared__ float sx[ROWS_PER * PP];
    if (tid < ROWS_PER * PP) sx[tid] = X[(size_t)n0 * PP + tid];
    __syncthreads();

    double acc = 0.0;
    for (int ni = 0; ni < ROWS_PER; ni++) {
        const int n = n0 + ni;
        const float lse  = g_lse[n];
        const float logs = g_logs[n];
        const float s    = g_s[n];
        float xb = mu_j;
#pragma unroll
        for (int p = 0; p < PP; p++) xb = fmaf(sx[ni * PP + p], b[p], xb);
        const float t   = xb - lse;            // log(pi)
        const float m   = s * expf(t);         // mean
        const float lrm = logf(r + m);         // log(r + mean)
        float y = valid ? Y[(size_t)n * JJ + j] : 0.0f;
        float term = 0.0f;
        if (valid) {
            int yi = (int)(y + 0.5f);          // Y is integer-valued
            float lgy1 = (yi >= 0 && yi < LFMAX) ? g_lf[yi] : lgammaf(y + 1.0f);
            term = lgammaf(y + r) - lgr - lgy1
                 + r * (logr - lrm)
                 + y * (logs + t - lrm);       // log(mean) = log s + t
        }
        acc += (double)term;
    }

    // block reduction of double acc
    const int lane = tid & 31, wid = tid >> 5;
    __shared__ double sd[8];
#pragma unroll
    for (int off = 16; off > 0; off >>= 1)
        acc += __shfl_down_sync(0xffffffffu, acc, off);
    if (lane == 0) sd[wid] = acc;
    __syncthreads();
    if (wid == 0) {
        double v = (lane < 8) ? sd[lane] : 0.0;
#pragma unroll
        for (int off = 4; off > 0; off >>= 1)
            v += __shfl_down_sync(0xffffffffu, v, off);
        if (lane == 0) g_part[blockIdx.y * JB + blockIdx.x] = v;
    }
}

// ---------------------------------------------------------------------------
// Kernel 5: deterministic final reduction -> float scalar
// ---------------------------------------------------------------------------
__global__ void k_finish(float* __restrict__ out) {
    const int tid = threadIdx.x;
    double a = 0.0;
    for (int i = tid; i < JB * RB; i += blockDim.x) a += g_part[i];
    const int lane = tid & 31, wid = tid >> 5;
    __shared__ double sd[8];
#pragma unroll
    for (int off = 16; off > 0; off >>= 1)
        a += __shfl_down_sync(0xffffffffu, a, off);
    if (lane == 0) sd[wid] = a;
    __syncthreads();
    if (wid == 0) {
        double v = (lane < 8) ? sd[lane] : 0.0;
#pragma unroll
        for (int off = 4; off > 0; off >>= 1)
            v += __shfl_down_sync(0xffffffffu, v, off);
        if (lane == 0) out[0] = (float)v;
    }
}

// ---------------------------------------------------------------------------
extern "C" void kernel_launch(void* const* d_in, const int* in_sizes, int n_in,
                              void* d_out, int out_size) {
    const float* mu   = (const float*)d_in[0];   // [DIMM]
    const float* beta = (const float*)d_in[1];   // [PP * DIMM]
    const float* phi  = (const float*)d_in[2];   // [JJ]
    const float* X    = (const float*)d_in[3];   // [NN, PP]
    const float* Y    = (const float*)d_in[4];   // [NN, JJ]
    float* out = (float*)d_out;

    k_prep<<<JB, JT>>>(phi);
    k_rowpart<<<dim3(JB, RB), JT>>>(mu, beta, X, Y);
    k_rowfinal<<<(NN + 255) / 256, 256>>>();
    k_main<<<dim3(JB, RB), JT>>>(mu, beta, X, Y);
    k_finish<<<1, 256>>>(out);
}

// round 12
// speedup vs baseline: 1.9151x; 1.9151x over previous
#include <cuda_runtime.h>
#include <math.h>

// Problem constants (fixed by the reference setup)
constexpr int NN   = 512;
constexpr int JJ   = 20000;
constexpr int DIMM = JJ - 1;
constexpr int PP   = 8;
constexpr int JT   = 256;                  // threads per block (j dimension)
constexpr int JB   = (JJ + JT - 1) / JT;   // 79 j-blocks
constexpr int RB   = 16;                   // row chunks
constexpr int ROWS = NN / RB;              // 32 rows per block
constexpr int W    = JB * 8;               // 632 per-warp partials per row
constexpr int LFMAX = 2048;                // log-factorial table size (Y <= 1000)

// Scratch (device globals: no allocations allowed)
__device__ float  g_rc[JJ * 2];    // interleaved (r, c) per gene; c = r*log r - lgamma(r) + 0.5*ln(2pi)
__device__ float  g_lf[LFMAX];     // lgamma(i+1)
__device__ float  g_pe[NN * W];    // per-(row, warp) partial sum exp(logit), row-major
__device__ float  g_py[NN * W];    // per-(row, warp) partial sum Y
__device__ float4 g_row[NN];       // {lse, log s, s, 0} per row
__device__ double g_part[JB * RB]; // per-block loglik partials

__device__ __forceinline__ float lg2f(float x){ float r; asm("lg2.approx.f32 %0, %1;" : "=f"(r) : "f"(x)); return r; }
__device__ __forceinline__ float ex2f(float x){ float r; asm("ex2.approx.f32 %0, %1;" : "=f"(r) : "f"(x)); return r; }
__device__ __forceinline__ float rcpf(float x){ float r; asm("rcp.approx.f32 %0, %1;" : "=f"(r) : "f"(x)); return r; }

// ---------------------------------------------------------------------------
// Kernel 1: per-gene precompute (precise math, one-time) + log-factorial table
// ---------------------------------------------------------------------------
__global__ void k_prep(const float* __restrict__ phi) {
    int i = blockIdx.x * blockDim.x + threadIdx.x;
    if (i < JJ) {
        float ph = phi[i];
        float sp = fmaxf(ph, 0.0f) + log1pf(expf(-fabsf(ph)));   // softplus
        float r  = 1.0f / sp;
        float logr = -logf(sp);
        float c = fmaf(r, logr, -lgammaf(r)) + 0.918938533f;     // + 0.5*ln(2*pi)
        g_rc[2 * i]     = r;
        g_rc[2 * i + 1] = c;
    }
    if (i < LFMAX) g_lf[i] = lgammaf((float)i + 1.0f);
}

// ---------------------------------------------------------------------------
// Kernel 2: j-major row stats: per-warp partial sum(exp(logit)) and sum(Y).
// No block reduction, no syncthreads in the loop.
// ---------------------------------------------------------------------------
__global__ void __launch_bounds__(JT) k_rowpart(const float* __restrict__ mu,
                                                const float* __restrict__ beta,
                                                const float* __restrict__ X,
                                                const float* __restrict__ Y) {
    const int tid = threadIdx.x;
    const int j   = blockIdx.x * JT + tid;
    const bool valid = (j < JJ);
    const bool hasb  = (j < DIMM);

    float mu_j = 0.0f;
    float b[PP];
#pragma unroll
    for (int p = 0; p < PP; p++) b[p] = 0.0f;
    if (hasb) {
        mu_j = mu[j];
#pragma unroll
        for (int p = 0; p < PP; p++) b[p] = beta[(size_t)p * DIMM + j];
    }

    const int n0 = blockIdx.y * ROWS;
    __shared__ float4 sx[ROWS * 2];                 // X rows as float4 pairs
    if (tid < ROWS * 2) sx[tid] = ((const float4*)(X + (size_t)n0 * PP))[tid];
    __syncthreads();

    const int lane = tid & 31, wid = tid >> 5;
    const int col  = blockIdx.x * 8 + wid;
    const float* yp = Y + (size_t)n0 * JJ + j;

#pragma unroll 4
    for (int ni = 0; ni < ROWS; ni++) {
        float4 xa = sx[2 * ni], xc = sx[2 * ni + 1];
        float xb = mu_j;
        xb = fmaf(xa.x, b[0], xb); xb = fmaf(xa.y, b[1], xb);
        xb = fmaf(xa.z, b[2], xb); xb = fmaf(xa.w, b[3], xb);
        xb = fmaf(xc.x, b[4], xb); xb = fmaf(xc.y, b[5], xb);
        xb = fmaf(xc.z, b[6], xb); xb = fmaf(xc.w, b[7], xb);
        // pivot column (j == DIMM): xb = 0 -> exp = 1 (correct)
        float e = valid ? ex2f(xb * 1.44269504f) : 0.0f;
        float y = valid ? *yp : 0.0f;
        yp += JJ;
#pragma unroll
        for (int off = 16; off > 0; off >>= 1) {
            e += __shfl_down_sync(0xffffffffu, e, off);
            y += __shfl_down_sync(0xffffffffu, y, off);
        }
        if (lane == 0) {
            int n = n0 + ni;
            g_pe[(size_t)n * W + col] = e;
            g_py[(size_t)n * W + col] = y;
        }
    }
}

// ---------------------------------------------------------------------------
// Kernel 3: finalize row stats. One block per row, coalesced 632-wide reduce.
// ---------------------------------------------------------------------------
__global__ void k_rowfinal() {
    const int n = blockIdx.x, tid = threadIdx.x;   // blockDim = 128
    double e = 0.0;
    float  ys = 0.0f;
    for (int c = tid; c < W; c += 128) {
        e  += (double)g_pe[(size_t)n * W + c];
        ys += g_py[(size_t)n * W + c];             // exact: integer sums < 2^24
    }
    const int lane = tid & 31, wid = tid >> 5;
    __shared__ double se[4];
    __shared__ float  sy[4];
#pragma unroll
    for (int off = 16; off > 0; off >>= 1) {
        e  += __shfl_down_sync(0xffffffffu, e, off);
        ys += __shfl_down_sync(0xffffffffu, ys, off);
    }
    if (lane == 0) { se[wid] = e; sy[wid] = ys; }
    __syncthreads();
    if (tid == 0) {
        double et = se[0] + se[1] + se[2] + se[3];
        float  st = sy[0] + sy[1] + sy[2] + sy[3];
        g_row[n] = make_float4((float)log(et), logf(st), st, 0.0f);
    }
}

// ---------------------------------------------------------------------------
// Kernel 4: main NB log-likelihood. Branchless shift-2 Stirling + MUFU approx.
// term = ln2*(A*lg2(z+2) - lg2(z(z+1)) - z*lg2(r+m))
//      + c_j - (z+2) + u*(1/12 - u^2/360) - lf[y] + y*(log s + t)
// where z = y + r, u = 1/(z+2), t = xb - lse, m = s*exp(t), A = z + 1.5
// ---------------------------------------------------------------------------
__global__ void __launch_bounds__(JT) k_main(const float* __restrict__ mu,
                                             const float* __restrict__ beta,
                                             const float* __restrict__ X,
                                             const float* __restrict__ Y) {
    const int tid = threadIdx.x;
    const int j   = blockIdx.x * JT + tid;
    const bool valid = (j < JJ);
    const bool hasb  = (j < DIMM);

    float r = 1.0f, cj = 0.0f;
    if (valid) {
        float2 rc = ((const float2*)g_rc)[j];
        r = rc.x; cj = rc.y;
    }
    float mu_j = 0.0f;
    float b[PP];
#pragma unroll
    for (int p = 0; p < PP; p++) b[p] = 0.0f;
    if (hasb) {
        mu_j = mu[j];
#pragma unroll
        for (int p = 0; p < PP; p++) b[p] = beta[(size_t)p * DIMM + j];
    }

    const int n0 = blockIdx.y * ROWS;
    __shared__ float4 sx[ROWS * 2];     // X rows
    __shared__ float4 srow[ROWS];       // {lse, logs, s}
    __shared__ float  slf[LFMAX];       // log-factorial table (8 KB)
    if (tid < ROWS * 2) sx[tid] = ((const float4*)(X + (size_t)n0 * PP))[tid];
    if (tid < ROWS)     srow[tid] = g_row[n0 + tid];
    for (int i = tid; i < LFMAX; i += JT) slf[i] = g_lf[i];
    __syncthreads();

    const float* yp = Y + (size_t)n0 * JJ + j;
    float acc = 0.0f;

#pragma unroll 4
    for (int ni = 0; ni < ROWS; ni++) {
        float4 xa = sx[2 * ni], xc = sx[2 * ni + 1];
        float4 rw = srow[ni];                       // x=lse y=logs z=s
        float xb = mu_j;
        xb = fmaf(xa.x, b[0], xb); xb = fmaf(xa.y, b[1], xb);
        xb = fmaf(xa.z, b[2], xb); xb = fmaf(xa.w, b[3], xb);
        xb = fmaf(xc.x, b[4], xb); xb = fmaf(xc.y, b[5], xb);
        xb = fmaf(xc.z, b[6], xb); xb = fmaf(xc.w, b[7], xb);

        float t  = xb - rw.x;                       // log(pi)
        float e  = ex2f(t * 1.44269504f);
        float m  = rw.z * e;                        // mean
        float rm = r + m;
        float l2rm = lg2f(rm);

        float y = valid ? *yp : 0.0f;
        yp += JJ;
        float z   = y + r;
        float z2  = z + 2.0f;
        float l2z2 = lg2f(z2);
        float u   = rcpf(z2);
        float pq  = fmaf(z, z, z);                  // z*(z+1)
        float l2pq = lg2f(pq);
        float u2  = u * u;
        float inner = fmaf(u2, -2.77777778e-3f, 8.33333333e-2f); // 1/12 - u^2/360

        int yi = (int)y;                            // Y integer-valued, exact
        float lf = slf[yi];
        float lt = rw.y + t;                        // log(mean) = logs + t

        float A  = z + 1.5f;
        float lg = fmaf(A, l2z2, -l2pq);
        lg = fmaf(-z, l2rm, lg);

        float base = cj - z2;
        base = fmaf(y, lt, base);
        base -= lf;
        base = fmaf(u, inner, base);
        float term = fmaf(0.69314718f, lg, base);
        if (valid) acc += term;
    }

    // block reduction (double) -> per-block partial
    const int lane = tid & 31, wid = tid >> 5;
    double d = (double)acc;
    __shared__ double sd[8];
#pragma unroll
    for (int off = 16; off > 0; off >>= 1)
        d += __shfl_down_sync(0xffffffffu, d, off);
    if (lane == 0) sd[wid] = d;
    __syncthreads();
    if (wid == 0) {
        double v = (lane < 8) ? sd[lane] : 0.0;
#pragma unroll
        for (int off = 4; off > 0; off >>= 1)
            v += __shfl_down_sync(0xffffffffu, v, off);
        if (lane == 0) g_part[blockIdx.y * JB + blockIdx.x] = v;
    }
}

// ---------------------------------------------------------------------------
// Kernel 5: deterministic final reduction -> float scalar
// ---------------------------------------------------------------------------
__global__ void k_finish(float* __restrict__ out) {
    const int tid = threadIdx.x;
    double a = 0.0;
    for (int i = tid; i < JB * RB; i += blockDim.x) a += g_part[i];
    const int lane = tid & 31, wid = tid >> 5;
    __shared__ double sd[8];
#pragma unroll
    for (int off = 16; off > 0; off >>= 1)
        a += __shfl_down_sync(0xffffffffu, a, off);
    if (lane == 0) sd[wid] = a;
    __syncthreads();
    if (wid == 0) {
        double v = (lane < 8) ? sd[lane] : 0.0;
#pragma unroll
        for (int off = 4; off > 0; off >>= 1)
            v += __shfl_down_sync(0xffffffffu, v, off);
        if (lane == 0) out[0] = (float)v;
    }
}

// ---------------------------------------------------------------------------
extern "C" void kernel_launch(void* const* d_in, const int* in_sizes, int n_in,
                              void* d_out, int out_size) {
    const float* mu   = (const float*)d_in[0];   // [DIMM]
    const float* beta = (const float*)d_in[1];   // [PP * DIMM]
    const float* phi  = (const float*)d_in[2];   // [JJ]
    const float* X    = (const float*)d_in[3];   // [NN, PP]
    const float* Y    = (const float*)d_in[4];   // [NN, JJ]
    float* out = (float*)d_out;

    k_prep<<<JB, JT>>>(phi);
    k_rowpart<<<dim3(JB, RB), JT>>>(mu, beta, X, Y);
    k_rowfinal<<<NN, 128>>>();
    k_main<<<dim3(JB, RB), JT>>>(mu, beta, X, Y);
    k_finish<<<1, 256>>>(out);
}

// round 13
// speedup vs baseline: 2.4122x; 1.2596x over previous
#include <cuda_runtime.h>
#include <math.h>

constexpr int NN   = 512;
constexpr int JJ   = 20000;
constexpr int DIMM = JJ - 1;
constexpr int PP   = 8;
constexpr int JT   = 256;
constexpr int JB   = (JJ + JT - 1) / JT;   // 79
constexpr int RB   = 16;
constexpr int ROWS = NN / RB;              // 32 rows per block
constexpr int NPAIR = ROWS / 2;            // 16 row pairs
constexpr int W    = JB * 8;               // 632 warp columns
constexpr int LFMAX = 2048;

constexpr float LOG2E = 1.4426950408889634f;
constexpr float LN2   = 0.6931471805599453f;

// Scratch (device globals)
__device__ float    g_rc[JJ * 2];     // (r, c) per gene; c = r*ln r - lnGamma(r) + 0.5*ln(2pi)
__device__ float    g_lf[LFMAX];      // lnGamma(i+1)
__device__ unsigned g_pe[NN * W];     // per-(row,warp) sum of exp(logit)*2^14, fixed point
__device__ unsigned g_py[NN * W];     // per-(row,warp) sum of Y (exact int)
__device__ float4   g_row[NN];        // {lse2 = log2(sum exp), logs2 = log2(s), s, 0}
__device__ double   g_part[JB * RB];

typedef unsigned long long ull;

__device__ __forceinline__ float lg2f(float x){ float r; asm("lg2.approx.f32 %0, %1;" : "=f"(r) : "f"(x)); return r; }
__device__ __forceinline__ float ex2f(float x){ float r; asm("ex2.approx.f32 %0, %1;" : "=f"(r) : "f"(x)); return r; }
__device__ __forceinline__ float rcpf(float x){ float r; asm("rcp.approx.f32 %0, %1;" : "=f"(r) : "f"(x)); return r; }
__device__ __forceinline__ ull  pk2(float lo, float hi){ ull r; asm("mov.b64 %0, {%1,%2};" : "=l"(r) : "f"(lo), "f"(hi)); return r; }
__device__ __forceinline__ void upk2(ull v, float& lo, float& hi){ asm("mov.b64 {%0,%1}, %2;" : "=f"(lo), "=f"(hi) : "l"(v)); }
__device__ __forceinline__ ull fma2(ull a, ull b, ull c){ ull d; asm("fma.rn.f32x2 %0, %1, %2, %3;" : "=l"(d) : "l"(a), "l"(b), "l"(c)); return d; }
__device__ __forceinline__ ull add2(ull a, ull b){ ull d; asm("add.rn.f32x2 %0, %1, %2;" : "=l"(d) : "l"(a), "l"(b)); return d; }
__device__ __forceinline__ ull mul2(ull a, ull b){ ull d; asm("mul.rn.f32x2 %0, %1, %2;" : "=l"(d) : "l"(a), "l"(b)); return d; }
__device__ __forceinline__ unsigned redux_add(unsigned v){ unsigned r; asm("redux.sync.add.u32 %0, %1, 0xffffffff;" : "=r"(r) : "r"(v)); return r; }

// ---------------------------------------------------------------------------
// Kernel 1: per-gene precompute (precise, one-time) + log-factorial table
// ---------------------------------------------------------------------------
__global__ void k_prep(const float* __restrict__ phi) {
    int i = blockIdx.x * blockDim.x + threadIdx.x;
    if (i < JJ) {
        float ph = phi[i];
        float sp = fmaxf(ph, 0.0f) + log1pf(expf(-fabsf(ph)));   // softplus
        float r  = 1.0f / sp;
        float logr = -logf(sp);
        float c = fmaf(r, logr, -lgammaf(r)) + 0.9189385332046727f;  // + 0.5*ln(2pi)
        g_rc[2 * i]     = r;
        g_rc[2 * i + 1] = c;
    }
    if (i < LFMAX) g_lf[i] = lgammaf((float)i + 1.0f);
}

// ---------------------------------------------------------------------------
// Kernel 2: row stats via redux.sync. e scaled by 2^14 (folded into ex2 arg),
// y exact integer. Zero shuffles, zero in-loop barriers. DRAM-bound.
// ---------------------------------------------------------------------------
__global__ void __launch_bounds__(JT) k_rowpart(const float* __restrict__ mu,
                                                const float* __restrict__ beta,
                                                const float* __restrict__ X,
                                                const float* __restrict__ Y) {
    const int tid = threadIdx.x;
    const int j   = blockIdx.x * JT + tid;
    const bool valid = (j < JJ);
    const bool hasb  = (j < DIMM);

    // mu,beta pre-scaled by log2(e); +14 folds the 2^14 fixed-point scale
    float mu2 = 14.0f;
    float b[PP];
#pragma unroll
    for (int p = 0; p < PP; p++) b[p] = 0.0f;
    if (hasb) {
        mu2 = fmaf(mu[j], LOG2E, 14.0f);
#pragma unroll
        for (int p = 0; p < PP; p++) b[p] = beta[(size_t)p * DIMM + j] * LOG2E;
    }

    const int n0 = blockIdx.y * ROWS;
    __shared__ float4 sx[ROWS * 2];
    if (tid < ROWS * 2) sx[tid] = ((const float4*)(X + (size_t)n0 * PP))[tid];
    __syncthreads();

    const int lane = tid & 31, wid = tid >> 5;
    const int col  = blockIdx.x * 8 + wid;
    const float* yp = Y + (size_t)n0 * JJ + (valid ? j : 0);

#pragma unroll 4
    for (int ni = 0; ni < ROWS; ni++) {
        float4 xa = sx[2 * ni], xc = sx[2 * ni + 1];
        float xb = mu2;
        xb = fmaf(xa.x, b[0], xb); xb = fmaf(xa.y, b[1], xb);
        xb = fmaf(xa.z, b[2], xb); xb = fmaf(xa.w, b[3], xb);
        xb = fmaf(xc.x, b[4], xb); xb = fmaf(xc.y, b[5], xb);
        xb = fmaf(xc.z, b[6], xb); xb = fmaf(xc.w, b[7], xb);
        float e = ex2f(xb);                        // exp(logit) * 2^14
        float y = *yp; yp += JJ;
        unsigned ei = valid ? __float2uint_rn(e) : 0u;
        unsigned yi = valid ? __float2uint_rn(y) : 0u;
        unsigned es = redux_add(ei);
        unsigned ys = redux_add(yi);
        if (lane == 0) {
            int n = n0 + ni;
            g_pe[(size_t)n * W + col] = es;
            g_py[(size_t)n * W + col] = ys;
        }
    }
}

// ---------------------------------------------------------------------------
// Kernel 3: finalize row stats. Exact integer sums (double holds < 2^53).
// ---------------------------------------------------------------------------
__global__ void k_rowfinal() {
    const int n = blockIdx.x, tid = threadIdx.x;   // 128 threads
    double e = 0.0;
    unsigned ys = 0;
    for (int c = tid; c < W; c += 128) {
        e  += (double)g_pe[(size_t)n * W + c];
        ys += g_py[(size_t)n * W + c];
    }
    const int lane = tid & 31, wid = tid >> 5;
    __shared__ double se[4];
    __shared__ unsigned sy[4];
#pragma unroll
    for (int off = 16; off > 0; off >>= 1) {
        e  += __shfl_down_sync(0xffffffffu, e, off);
        ys += __shfl_down_sync(0xffffffffu, ys, off);
    }
    if (lane == 0) { se[wid] = e; sy[wid] = ys; }
    __syncthreads();
    if (tid == 0) {
        double et = se[0] + se[1] + se[2] + se[3];
        unsigned st = sy[0] + sy[1] + sy[2] + sy[3];
        float s = (float)st;
        g_row[n] = make_float4((float)(log2(et) - 14.0), log2f(s), s, 0.0f);
    }
}

// ---------------------------------------------------------------------------
// Kernel 4: main NB log-likelihood. Direct Stirling (no shift), f32x2 packed
// arithmetic over row pairs, log2-domain logits. 4 MUFU / element.
// term = ln2*[(z-0.5)*lg2(z) - z*lg2(r+m) + y*(logs2+t2)] + cj - z + 1/(12z) - lf[y]
// ---------------------------------------------------------------------------
__global__ void __launch_bounds__(JT) k_main(const float* __restrict__ mu,
                                             const float* __restrict__ beta,
                                             const float* __restrict__ X,
                                             const float* __restrict__ Y) {
    const int tid = threadIdx.x;
    const int j   = blockIdx.x * JT + tid;
    const bool valid = (j < JJ);
    const bool hasb  = (j < DIMM);

    float r = 1.0f, cj = 0.0f;
    if (valid) {
        float2 rc = ((const float2*)g_rc)[j];
        r = rc.x; cj = rc.y;
    }
    float mu2 = 0.0f;
    ull b2[PP];
#pragma unroll
    for (int p = 0; p < PP; p++) b2[p] = 0ull;
    if (hasb) {
        mu2 = mu[j] * LOG2E;
#pragma unroll
        for (int p = 0; p < PP; p++) {
            float v = beta[(size_t)p * DIMM + j] * LOG2E;
            b2[p] = pk2(v, v);
        }
    }

    const int n0 = blockIdx.y * ROWS;
    __shared__ ull  s_x2[NPAIR * PP];   // X packed per row-pair
    __shared__ ull  s_nl[NPAIR];        // -lse2 pair
    __shared__ ull  s_g2[NPAIR];        // logs2 pair
    __shared__ ull  s_s2[NPAIR];        // s pair
    __shared__ float slf[LFMAX];        // lnGamma(y+1) table (8 KB)
    if (tid < NPAIR * PP) {
        int q = tid >> 3, p = tid & 7;
        s_x2[tid] = pk2(X[(size_t)(n0 + 2 * q) * PP + p],
                        X[(size_t)(n0 + 2 * q + 1) * PP + p]);
    }
    if (tid < NPAIR) {
        float4 ra = g_row[n0 + 2 * tid], rb = g_row[n0 + 2 * tid + 1];
        s_nl[tid] = pk2(-ra.x, -rb.x);
        s_g2[tid] = pk2(ra.y, rb.y);
        s_s2[tid] = pk2(ra.z, rb.z);
    }
    for (int i = tid; i < LFMAX; i += JT) slf[i] = g_lf[i];
    __syncthreads();

    const ull mu2b = pk2(mu2, mu2);
    const ull r2b  = pk2(r, r);
    const ull cjb  = pk2(cj, cj);
    const ull cm1  = pk2(-1.0f, -1.0f);
    const ull cmh  = pk2(-0.5f, -0.5f);
    const ull c12  = pk2(8.3333333e-2f, 8.3333333e-2f);
    const ull ln2b = pk2(LN2, LN2);

    const float* yp = Y + (size_t)n0 * JJ + (valid ? j : 0);
    ull acc2 = 0ull;

#pragma unroll 4
    for (int q = 0; q < NPAIR; q++) {
        ull xb2 = mu2b;
#pragma unroll
        for (int p = 0; p < PP; p++) xb2 = fma2(s_x2[q * PP + p], b2[p], xb2);
        ull t2 = add2(xb2, s_nl[q]);              // log2(pi)
        float t0, t1; upk2(t2, t0, t1);
        float e0 = ex2f(t0), e1 = ex2f(t1);       // pi
        ull m2 = mul2(s_s2[q], pk2(e0, e1));      // mean
        ull rm2 = add2(m2, r2b);
        float rm0, rm1; upk2(rm2, rm0, rm1);
        float lr0 = lg2f(rm0), lr1 = lg2f(rm1);

        float y0 = yp[0], y1 = yp[JJ]; yp += 2 * JJ;
        ull y2 = pk2(y0, y1);
        ull z2 = add2(y2, r2b);
        float z0, z1; upk2(z2, z0, z1);
        float lz0 = lg2f(z0), lz1 = lg2f(z1);
        float u0 = rcpf(z0), u1 = rcpf(z1);
        float lf0 = slf[(int)y0], lf1 = slf[(int)y1];

        ull lzp = pk2(lz0, lz1);
        ull lrp = pk2(lr0, lr1);
        ull d2  = fma2(lrp, cm1, lzp);            // lg2(z) - lg2(rm)
        ull G   = mul2(z2, d2);
        G = fma2(lzp, cmh, G);                    // -0.5*lg2(z)
        ull lt2 = add2(s_g2[q], t2);              // log2(mean)
        G = fma2(y2, lt2, G);
        ull H = fma2(z2, cm1, cjb);               // cj - z
        H = fma2(pk2(u0, u1), c12, H);            // + 1/(12z)
        H = fma2(pk2(lf0, lf1), cm1, H);          // - lf[y]
        acc2 = add2(acc2, fma2(ln2b, G, H));
    }

    float a0, a1; upk2(acc2, a0, a1);
    double d = valid ? (double)a0 + (double)a1 : 0.0;

    const int lane = tid & 31, wid = tid >> 5;
    __shared__ double sd[8];
#pragma unroll
    for (int off = 16; off > 0; off >>= 1)
        d += __shfl_down_sync(0xffffffffu, d, off);
    if (lane == 0) sd[wid] = d;
    __syncthreads();
    if (wid == 0) {
        double v = (lane < 8) ? sd[lane] : 0.0;
#pragma unroll
        for (int off = 4; off > 0; off >>= 1)
            v += __shfl_down_sync(0xffffffffu, v, off);
        if (lane == 0) g_part[blockIdx.y * JB + blockIdx.x] = v;
    }
}

// ---------------------------------------------------------------------------
// Kernel 5: deterministic final reduction -> float scalar
// ---------------------------------------------------------------------------
__global__ void k_finish(float* __restrict__ out) {
    const int tid = threadIdx.x;
    double a = 0.0;
    for (int i = tid; i < JB * RB; i += blockDim.x) a += g_part[i];
    const int lane = tid & 31, wid = tid >> 5;
    __shared__ double sd[8];
#pragma unroll
    for (int off = 16; off > 0; off >>= 1)
        a += __shfl_down_sync(0xffffffffu, a, off);
    if (lane == 0) sd[wid] = a;
    __syncthreads();
    if (wid == 0) {
        double v = (lane < 8) ? sd[lane] : 0.0;
#pragma unroll
        for (int off = 4; off > 0; off >>= 1)
            v += __shfl_down_sync(0xffffffffu, v, off);
        if (lane == 0) out[0] = (float)v;
    }
}

// ---------------------------------------------------------------------------
extern "C" void kernel_launch(void* const* d_in, const int* in_sizes, int n_in,
                              void* d_out, int out_size) {
    const float* mu   = (const float*)d_in[0];
    const float* beta = (const float*)d_in[1];
    const float* phi  = (const float*)d_in[2];
    const float* X    = (const float*)d_in[3];
    const float* Y    = (const float*)d_in[4];
    float* out = (float*)d_out;

    k_prep<<<JB, JT>>>(phi);
    k_rowpart<<<dim3(JB, RB), JT>>>(mu, beta, X, Y);
    k_rowfinal<<<NN, 128>>>();
    k_main<<<dim3(JB, RB), JT>>>(mu, beta, X, Y);
    k_finish<<<1, 256>>>(out);
}

// round 14
// speedup vs baseline: 2.5458x; 1.0554x over previous
#include <cuda_runtime.h>
#include <math.h>

constexpr int NN   = 512;
constexpr int JJ   = 20000;
constexpr int DIMM = JJ - 1;
constexpr int PP   = 8;
constexpr int JT   = 256;
constexpr int JB   = (JJ + JT - 1) / JT;   // 79
constexpr int RB   = 16;
constexpr int ROWS = NN / RB;              // 32 rows per block
constexpr int NPAIR = ROWS / 2;            // 16 row pairs
constexpr int W    = JB * 8;               // 632 warp columns
constexpr int LFMAX = 2048;
constexpr int GRID = JB * RB;              // 1264

constexpr float LOG2E = 1.4426950408889634f;
constexpr float LN2   = 0.6931471805599453f;

// Scratch (device globals)
__device__ float    g_rc[JJ * 2];     // (r, c); c = r*ln r - lnGamma(r) + 0.5*ln(2pi)
__device__ float    g_lf[LFMAX];      // -lnGamma(i+1) + 1/(12*(i+1.44))  [pre-negated, with Stirling corr]
__device__ unsigned g_pe[NN * W];     // per-(row,warp) sum exp(logit)*2^14 fixed point
__device__ unsigned g_py[NN * W];     // per-(row,warp) sum Y (exact int)
__device__ float4   g_row[NN];        // {lse2, logs2, s, 0}
__device__ double   g_part[GRID];
__device__ unsigned g_done;           // last-block counter (self-resetting)

typedef unsigned long long ull;

__device__ __forceinline__ float lg2f(float x){ float r; asm("lg2.approx.f32 %0, %1;" : "=f"(r) : "f"(x)); return r; }
__device__ __forceinline__ float ex2f(float x){ float r; asm("ex2.approx.f32 %0, %1;" : "=f"(r) : "f"(x)); return r; }
__device__ __forceinline__ ull  pk2(float lo, float hi){ ull r; asm("mov.b64 %0, {%1,%2};" : "=l"(r) : "f"(lo), "f"(hi)); return r; }
__device__ __forceinline__ void upk2(ull v, float& lo, float& hi){ asm("mov.b64 {%0,%1}, %2;" : "=f"(lo), "=f"(hi) : "l"(v)); }
__device__ __forceinline__ ull fma2(ull a, ull b, ull c){ ull d; asm("fma.rn.f32x2 %0, %1, %2, %3;" : "=l"(d) : "l"(a), "l"(b), "l"(c)); return d; }
__device__ __forceinline__ ull add2(ull a, ull b){ ull d; asm("add.rn.f32x2 %0, %1, %2;" : "=l"(d) : "l"(a), "l"(b)); return d; }
__device__ __forceinline__ ull mul2(ull a, ull b){ ull d; asm("mul.rn.f32x2 %0, %1, %2;" : "=l"(d) : "l"(a), "l"(b)); return d; }
__device__ __forceinline__ unsigned redux_add(unsigned v){ unsigned r; asm("redux.sync.add.u32 %0, %1, 0xffffffff;" : "=r"(r) : "r"(v)); return r; }

// ---------------------------------------------------------------------------
// Kernel 1: row stats via redux.sync (fixed-point exp, exact int Y), with the
// per-gene precompute fused into the blockIdx.y==0 wave (consumed only by K3).
// ---------------------------------------------------------------------------
__global__ void __launch_bounds__(JT) k_rowpart(const float* __restrict__ mu,
                                                const float* __restrict__ beta,
                                                const float* __restrict__ phi,
                                                const float* __restrict__ X,
                                                const float* __restrict__ Y) {
    const int tid = threadIdx.x;
    const int j   = blockIdx.x * JT + tid;
    const bool valid = (j < JJ);
    const bool hasb  = (j < DIMM);

    // ---- fused one-time per-gene precompute (precise math) ----
    if (blockIdx.y == 0) {
        if (valid) {
            float ph = phi[j];
            float sp = fmaxf(ph, 0.0f) + log1pf(expf(-fabsf(ph)));   // softplus
            float r  = 1.0f / sp;
            float c  = fmaf(r, -logf(sp), -lgammaf(r)) + 0.9189385332046727f;
            g_rc[2 * j]     = r;
            g_rc[2 * j + 1] = c;
        }
        if (j < LFMAX)
            g_lf[j] = -lgammaf((float)j + 1.0f) + 1.0f / (12.0f * ((float)j + 1.44f));
    }

    // mu,beta pre-scaled by log2(e); +14 folds the 2^14 fixed-point scale
    float mu2 = 14.0f;
    float b[PP];
#pragma unroll
    for (int p = 0; p < PP; p++) b[p] = 0.0f;
    if (hasb) {
        mu2 = fmaf(mu[j], LOG2E, 14.0f);
#pragma unroll
        for (int p = 0; p < PP; p++) b[p] = beta[(size_t)p * DIMM + j] * LOG2E;
    }

    const int n0 = blockIdx.y * ROWS;
    __shared__ float4 sx[ROWS * 2];
    if (tid < ROWS * 2) sx[tid] = ((const float4*)(X + (size_t)n0 * PP))[tid];
    __syncthreads();

    const int lane = tid & 31, wid = tid >> 5;
    const int col  = blockIdx.x * 8 + wid;
    const float* yp = Y + (size_t)n0 * JJ + (valid ? j : 0);

#pragma unroll 4
    for (int ni = 0; ni < ROWS; ni++) {
        float4 xa = sx[2 * ni], xc = sx[2 * ni + 1];
        float xb = mu2;
        xb = fmaf(xa.x, b[0], xb); xb = fmaf(xa.y, b[1], xb);
        xb = fmaf(xa.z, b[2], xb); xb = fmaf(xa.w, b[3], xb);
        xb = fmaf(xc.x, b[4], xb); xb = fmaf(xc.y, b[5], xb);
        xb = fmaf(xc.z, b[6], xb); xb = fmaf(xc.w, b[7], xb);
        float e = ex2f(xb);                        // exp(logit) * 2^14
        float y = *yp; yp += JJ;
        unsigned ei = valid ? __float2uint_rn(e) : 0u;
        unsigned yi = valid ? __float2uint_rn(y) : 0u;
        unsigned es = redux_add(ei);
        unsigned ys = redux_add(yi);
        if (lane == 0) {
            int n = n0 + ni;
            g_pe[(size_t)n * W + col] = es;
            g_py[(size_t)n * W + col] = ys;
        }
    }
}

// ---------------------------------------------------------------------------
// Kernel 2: finalize row stats (exact integer sums in double).
// ---------------------------------------------------------------------------
__global__ void k_rowfinal() {
    const int n = blockIdx.x, tid = threadIdx.x;   // 128 threads
    double e = 0.0;
    unsigned ys = 0;
    for (int c = tid; c < W; c += 128) {
        e  += (double)g_pe[(size_t)n * W + c];
        ys += g_py[(size_t)n * W + c];
    }
    const int lane = tid & 31, wid = tid >> 5;
    __shared__ double se[4];
    __shared__ unsigned sy[4];
#pragma unroll
    for (int off = 16; off > 0; off >>= 1) {
        e  += __shfl_down_sync(0xffffffffu, e, off);
        ys += __shfl_down_sync(0xffffffffu, ys, off);
    }
    if (lane == 0) { se[wid] = e; sy[wid] = ys; }
    __syncthreads();
    if (tid == 0) {
        double et = se[0] + se[1] + se[2] + se[3];
        unsigned st = sy[0] + sy[1] + sy[2] + sy[3];
        float s = (float)st;
        g_row[n] = make_float4((float)(log2(et) - 14.0), log2f(s), s, 0.0f);
    }
}

// ---------------------------------------------------------------------------
// Kernel 3: main NB loglik, f32x2 packed, 3 MUFU/element, fused final reduce.
// term = ln2*[(z-0.5)lg2 z - z*lg2(r+m) + y*(logs2+t2)] + cj - z + slf[y]
//   (slf pre-negated lnGamma(y+1) with folded 1/(12z)~1/(12(y+1.44)) correction)
// ---------------------------------------------------------------------------
__global__ void __launch_bounds__(JT, 5) k_main(const float* __restrict__ mu,
                                                const float* __restrict__ beta,
                                                const float* __restrict__ Y,
                                                const float* __restrict__ X,
                                                float* __restrict__ out) {
    const int tid = threadIdx.x;
    const int j   = blockIdx.x * JT + tid;
    const bool valid = (j < JJ);
    const bool hasb  = (j < DIMM);

    float r = 1.0f, cj = 0.0f;
    if (valid) {
        float2 rc = ((const float2*)g_rc)[j];
        r = rc.x; cj = rc.y;
    }
    float mu2 = 0.0f;
    ull b2[PP];
#pragma unroll
    for (int p = 0; p < PP; p++) b2[p] = 0ull;
    if (hasb) {
        mu2 = mu[j] * LOG2E;
#pragma unroll
        for (int p = 0; p < PP; p++) {
            float v = beta[(size_t)p * DIMM + j] * LOG2E;
            b2[p] = pk2(v, v);
        }
    }

    const int n0 = blockIdx.y * ROWS;
    __shared__ ulonglong2 s_x2[NPAIR * 4];   // X packed: row-pair x covariate-pair
    __shared__ ulonglong2 s_ng[NPAIR];       // {(-lse2 pair), (logs2 pair)}
    __shared__ ull        s_s2[NPAIR];       // s pair
    __shared__ float      slf[LFMAX];        // pre-negated log-factorial (8 KB)
    if (tid < NPAIR * 4) {
        int q = tid >> 2, pp = tid & 3;
        const float* xa = X + (size_t)(n0 + 2 * q) * PP + 2 * pp;
        const float* xb = xa + PP;
        s_x2[tid] = make_ulonglong2(pk2(xa[0], xb[0]), pk2(xa[1], xb[1]));
    }
    if (tid < NPAIR) {
        float4 ra = g_row[n0 + 2 * tid], rb = g_row[n0 + 2 * tid + 1];
        s_ng[tid] = make_ulonglong2(pk2(-ra.x, -rb.x), pk2(ra.y, rb.y));
        s_s2[tid] = pk2(ra.z, rb.z);
    }
    for (int i = tid; i < LFMAX; i += JT) slf[i] = g_lf[i];
    __syncthreads();

    const ull mu2b = pk2(mu2, mu2);
    const ull r2b  = pk2(r, r);
    const ull cjb  = pk2(cj, cj);
    const ull cm1  = pk2(-1.0f, -1.0f);
    const ull cmh  = pk2(-0.5f, -0.5f);
    const ull ln2b = pk2(LN2, LN2);

    const float* yp = Y + (size_t)n0 * JJ + (valid ? j : 0);
    ull acc2 = 0ull;

#pragma unroll 2
    for (int q = 0; q < NPAIR; q++) {
        ulonglong2 x0 = s_x2[q * 4 + 0], x1 = s_x2[q * 4 + 1];
        ulonglong2 x2 = s_x2[q * 4 + 2], x3 = s_x2[q * 4 + 3];
        ull xb2 = mu2b;
        xb2 = fma2(x0.x, b2[0], xb2); xb2 = fma2(x0.y, b2[1], xb2);
        xb2 = fma2(x1.x, b2[2], xb2); xb2 = fma2(x1.y, b2[3], xb2);
        xb2 = fma2(x2.x, b2[4], xb2); xb2 = fma2(x2.y, b2[5], xb2);
        xb2 = fma2(x3.x, b2[6], xb2); xb2 = fma2(x3.y, b2[7], xb2);

        ulonglong2 ng = s_ng[q];
        ull t2 = add2(xb2, ng.x);                 // log2(pi)
        float t0, t1; upk2(t2, t0, t1);
        float e0 = ex2f(t0), e1 = ex2f(t1);       // pi
        ull rm2 = fma2(s_s2[q], pk2(e0, e1), r2b); // r + mean
        float rm0, rm1; upk2(rm2, rm0, rm1);
        ull lr = pk2(lg2f(rm0), lg2f(rm1));

        float y0 = yp[0], y1 = yp[JJ]; yp += 2 * JJ;
        ull y2 = pk2(y0, y1);
        ull z2 = add2(y2, r2b);
        float z0, z1; upk2(z2, z0, z1);
        ull lz = pk2(lg2f(z0), lg2f(z1));
        ull lf = pk2(slf[(int)y0], slf[(int)y1]);

        ull d  = fma2(lr, cm1, lz);               // lg2 z - lg2 rm
        ull G  = mul2(z2, d);
        G = fma2(lz, cmh, G);                     // -0.5*lg2 z
        ull lt2 = add2(ng.y, t2);                 // log2(mean)
        G = fma2(y2, lt2, G);
        ull H = fma2(z2, cm1, cjb);               // cj - z
        H = add2(H, lf);                          // - lnGamma(y+1) + corr
        acc2 = add2(acc2, fma2(ln2b, G, H));
    }

    float a0, a1; upk2(acc2, a0, a1);
    double d = valid ? (double)a0 + (double)a1 : 0.0;

    const int lane = tid & 31, wid = tid >> 5;
    __shared__ double sd[8];
#pragma unroll
    for (int off = 16; off > 0; off >>= 1)
        d += __shfl_down_sync(0xffffffffu, d, off);
    if (lane == 0) sd[wid] = d;
    __syncthreads();
    if (wid == 0) {
        double v = (lane < 8) ? sd[lane] : 0.0;
#pragma unroll
        for (int off = 4; off > 0; off >>= 1)
            v += __shfl_down_sync(0xffffffffu, v, off);
        if (lane == 0) g_part[blockIdx.y * JB + blockIdx.x] = v;
    }

    // ---- fused final reduction: last block to finish sums all partials ----
    __shared__ bool s_last;
    __threadfence();
    if (tid == 0) s_last = (atomicAdd(&g_done, 1u) == GRID - 1);
    __syncthreads();
    if (s_last) {
        double a = 0.0;
        for (int i = tid; i < GRID; i += JT) a += g_part[i];
#pragma unroll
        for (int off = 16; off > 0; off >>= 1)
            a += __shfl_down_sync(0xffffffffu, a, off);
        if (lane == 0) sd[wid] = a;
        __syncthreads();
        if (wid == 0) {
            double v = (lane < 8) ? sd[lane] : 0.0;
#pragma unroll
            for (int off = 4; off > 0; off >>= 1)
                v += __shfl_down_sync(0xffffffffu, v, off);
            if (lane == 0) { out[0] = (float)v; g_done = 0u; }
        }
    }
}

// ---------------------------------------------------------------------------
extern "C" void kernel_launch(void* const* d_in, const int* in_sizes, int n_in,
                              void* d_out, int out_size) {
    const float* mu   = (const float*)d_in[0];
    const float* beta = (const float*)d_in[1];
    const float* phi  = (const float*)d_in[2];
    const float* X    = (const float*)d_in[3];
    const float* Y    = (const float*)d_in[4];
    float* out = (float*)d_out;

    k_rowpart<<<dim3(JB, RB), JT>>>(mu, beta, phi, X, Y);
    k_rowfinal<<<NN, 128>>>();
    k_main<<<dim3(JB, RB), JT>>>(mu, beta, Y, X, out);
}